// round 1
// baseline (speedup 1.0000x reference)
#include <cuda_runtime.h>
#include <cuda_bf16.h>
#include <cstdint>

#define N_NODES 50000
#define N_EDGES 800000
#define EA (N_EDGES + N_NODES)      // 850000 edges incl. self loops
#define M_PAD 50048                  // 391 * 128
#define IN_CH 16
#define HID 64
#define HEADS 4
#define F1 256                       // HEADS*HID
#define OUT_CH 8
#define NEG_SLOPE 0.2f

// ---------------- device scratch (static; no allocations allowed) ------------
__device__ float g_bufA[(size_t)M_PAD * F1];   // h (gemm output) both layers
__device__ float g_bufB[(size_t)M_PAD * F1];   // act1 (256-wide) then act2 (64-wide)
__device__ float g_asrc[(size_t)M_PAD * HEADS];
__device__ float g_adst[(size_t)M_PAD * HEADS];
__device__ int   g_rowptr[N_NODES + 1];
__device__ int   g_cursor[N_NODES];
__device__ int   g_count[N_NODES];
__device__ int   g_csr_src[EA];
__device__ int   g_is64;

// ---------------- small helpers ---------------------------------------------
__device__ __forceinline__ float lrelu(float x) { return x > 0.f ? x : NEG_SLOPE * x; }
__device__ __forceinline__ float elu(float x)   { return x > 0.f ? x : expm1f(x); }

// ---------------- init: zero counts + pad rows of bufB -----------------------
__global__ void k_init() {
    int i = blockIdx.x * blockDim.x + threadIdx.x;
    if (i < N_NODES) g_count[i] = 0;
    if (i < (M_PAD - N_NODES) * F1) g_bufB[(size_t)N_NODES * F1 + i] = 0.f;
}

// ---------------- detect edge_index dtype (int32 vs int64) -------------------
__global__ void k_detect(const void* ei) {
    if (threadIdx.x == 0) {
        const int* e32 = (const int*)ei;
        bool is64 = true;
        #pragma unroll
        for (int j = 0; j < 16; j++)
            if (e32[2 * j + 1] != 0) is64 = false;
        g_is64 = is64 ? 1 : 0;
    }
}

__device__ __forceinline__ void load_edge(const void* ei, int i, int& s, int& d) {
    if (i < N_EDGES) {
        if (g_is64) {
            const long long* e = (const long long*)ei;
            s = (int)e[i]; d = (int)e[N_EDGES + i];
        } else {
            const int* e = (const int*)ei;
            s = e[i]; d = e[N_EDGES + i];
        }
    } else {
        s = d = i - N_EDGES;   // self loop
    }
}

// ---------------- CSR build --------------------------------------------------
__global__ void k_count(const void* ei) {
    int i = blockIdx.x * blockDim.x + threadIdx.x;
    if (i >= EA) return;
    int s, d; load_edge(ei, i, s, d);
    atomicAdd(&g_count[d], 1);
}

__global__ void k_scan() {   // single block, 1024 threads
    __shared__ int wsum[32];
    __shared__ int carry_s;
    int lane = threadIdx.x & 31, wid = threadIdx.x >> 5;
    if (threadIdx.x == 0) carry_s = 0;
    __syncthreads();
    for (int base = 0; base < N_NODES; base += 1024) {
        int i = base + threadIdx.x;
        int v = (i < N_NODES) ? g_count[i] : 0;
        int x = v;
        #pragma unroll
        for (int o = 1; o < 32; o <<= 1) {
            int t = __shfl_up_sync(~0u, x, o);
            if (lane >= o) x += t;
        }
        if (lane == 31) wsum[wid] = x;
        __syncthreads();
        if (wid == 0) {
            int y = wsum[lane];
            #pragma unroll
            for (int o = 1; o < 32; o <<= 1) {
                int t = __shfl_up_sync(~0u, y, o);
                if (lane >= o) y += t;
            }
            wsum[lane] = y;
        }
        __syncthreads();
        int wadd = wid ? wsum[wid - 1] : 0;
        int excl = carry_s + x + wadd - v;
        int total = wsum[31];
        if (i < N_NODES) { g_rowptr[i] = excl; g_cursor[i] = excl; }
        __syncthreads();
        if (threadIdx.x == 0) carry_s += total;
        __syncthreads();
    }
    if (threadIdx.x == 0) g_rowptr[N_NODES] = carry_s;
}

__global__ void k_scatter(const void* ei) {
    int i = blockIdx.x * blockDim.x + threadIdx.x;
    if (i >= EA) return;
    int s, d; load_edge(ei, i, s, d);
    int pos = atomicAdd(&g_cursor[d], 1);
    g_csr_src[pos] = s;
}

// ---------------- GEMM1: x[50000,16] @ W1[16,256] -> bufA --------------------
__global__ void k_gemm1(const float* __restrict__ x, const float* __restrict__ W1) {
    __shared__ float Ws[16 * 256];
    __shared__ float xs[16 * 16];
    int tid = threadIdx.x;
    int r0 = blockIdx.x * 16;
    for (int i = tid; i < 16 * 256; i += 256) Ws[i] = W1[i];
    {
        int r = r0 + (tid >> 4), c = tid & 15;
        xs[tid] = (r < N_NODES) ? x[r * IN_CH + c] : 0.f;
    }
    __syncthreads();
    for (int rr = 0; rr < 16; rr++) {
        float acc = 0.f;
        #pragma unroll
        for (int k = 0; k < 16; k++) acc += xs[rr * 16 + k] * Ws[k * 256 + tid];
        g_bufA[(size_t)(r0 + rr) * F1 + tid] = acc;
    }
}

// ---------------- alpha: per (node, head) dot products on bufA ---------------
__global__ void k_alpha(const float* __restrict__ a_src, const float* __restrict__ a_dst) {
    int gw = (blockIdx.x * blockDim.x + threadIdx.x) >> 5;
    int lane = threadIdx.x & 31;
    if (gw >= N_NODES * HEADS) return;
    int n = gw >> 2, hh = gw & 3;
    const float* hp = g_bufA + (size_t)n * F1 + hh * HID;
    const float* as = a_src + hh * HID;
    const float* ad = a_dst + hh * HID;
    float x0 = hp[lane], x1 = hp[lane + 32];
    float ps = x0 * as[lane] + x1 * as[lane + 32];
    float pd = x0 * ad[lane] + x1 * ad[lane + 32];
    #pragma unroll
    for (int o = 16; o; o >>= 1) {
        ps += __shfl_xor_sync(~0u, ps, o);
        pd += __shfl_xor_sync(~0u, pd, o);
    }
    if (lane == 0) { g_asrc[n * 4 + hh] = ps; g_adst[n * 4 + hh] = pd; }
}

// ---------------- edge aggregation: one warp per destination node ------------
// LAYER 1: concat -> writes bufB [n,256] (bias b1, ELU)
// LAYER 2: mean over heads -> writes bufB [n,64] (bias b2, ELU)
template <int LAYER>
__global__ void k_edge_agg(const float* __restrict__ bias) {
    int warp = (blockIdx.x * blockDim.x + threadIdx.x) >> 5;
    int lane = threadIdx.x & 31;
    if (warp >= N_NODES) return;
    int dst = warp;
    int beg = g_rowptr[dst], end = g_rowptr[dst + 1];
    int hh = lane >> 3;                      // head owned by this lane group
    float ad = g_adst[dst * 4 + hh];

    // pass 1: per-head max over incoming edges (8 lanes per head in parallel)
    float m = -3.0e38f;
    for (int k = beg + (lane & 7); k < end; k += 8) {
        int s = g_csr_src[k];
        float e = lrelu(g_asrc[s * 4 + hh] + ad);
        m = fmaxf(m, e);
    }
    m = fmaxf(m, __shfl_xor_sync(~0u, m, 1));
    m = fmaxf(m, __shfl_xor_sync(~0u, m, 2));
    m = fmaxf(m, __shfl_xor_sync(~0u, m, 4));

    // pass 2: weighted aggregation. lane owns channels lane*8 .. lane*8+7
    float acc[8] = {0, 0, 0, 0, 0, 0, 0, 0};
    float den = 0.f;
    for (int k = beg; k < end; k++) {
        int s = g_csr_src[k];                                  // broadcast
        float e = lrelu(g_asrc[s * 4 + hh] + ad);
        float w = __expf(e - m);
        den += w;
        const float4* hr = (const float4*)(g_bufA + (size_t)s * F1 + lane * 8);
        float4 p = hr[0], q = hr[1];
        acc[0] += p.x * w; acc[1] += p.y * w; acc[2] += p.z * w; acc[3] += p.w * w;
        acc[4] += q.x * w; acc[5] += q.y * w; acc[6] += q.z * w; acc[7] += q.w * w;
    }
    float inv = 1.f / den;   // self loop guarantees den > 0

    if (LAYER == 1) {
        int c = lane * 8;
        float4 o0, o1;
        o0.x = elu(acc[0] * inv + bias[c + 0]);
        o0.y = elu(acc[1] * inv + bias[c + 1]);
        o0.z = elu(acc[2] * inv + bias[c + 2]);
        o0.w = elu(acc[3] * inv + bias[c + 3]);
        o1.x = elu(acc[4] * inv + bias[c + 4]);
        o1.y = elu(acc[5] * inv + bias[c + 5]);
        o1.z = elu(acc[6] * inv + bias[c + 6]);
        o1.w = elu(acc[7] * inv + bias[c + 7]);
        float4* op = (float4*)(g_bufB + (size_t)dst * F1 + c);
        op[0] = o0; op[1] = o1;
    } else {
        float v[8];
        #pragma unroll
        for (int j = 0; j < 8; j++) {
            v[j] = acc[j] * inv;
            v[j] += __shfl_xor_sync(~0u, v[j], 8);
            v[j] += __shfl_xor_sync(~0u, v[j], 16);
        }
        if (lane < 8) {
            int c = lane * 8;
            float4 o0, o1;
            o0.x = elu(v[0] * 0.25f + bias[c + 0]);
            o0.y = elu(v[1] * 0.25f + bias[c + 1]);
            o0.z = elu(v[2] * 0.25f + bias[c + 2]);
            o0.w = elu(v[3] * 0.25f + bias[c + 3]);
            o1.x = elu(v[4] * 0.25f + bias[c + 4]);
            o1.y = elu(v[5] * 0.25f + bias[c + 5]);
            o1.z = elu(v[6] * 0.25f + bias[c + 6]);
            o1.w = elu(v[7] * 0.25f + bias[c + 7]);
            float4* op = (float4*)(g_bufB + (size_t)dst * HID + c);
            op[0] = o0; op[1] = o1;
        }
    }
}

// ---------------- GEMM2: bufB[M_PAD,256] @ W2[256,256] -> bufA ---------------
#define BM 128
#define BN 128
#define BK 8
#define TM 8
#define TN 8
__global__ void __launch_bounds__(256, 2) k_gemm2(const float* __restrict__ W2) {
    __shared__ float As[BK][BM];
    __shared__ float Bs[BK][BN];
    int bx = blockIdx.x;          // 0..1  (N=256 / BN)
    int by = blockIdx.y;          // 0..390
    int tid = threadIdx.x;
    int ty = tid >> 4, tx = tid & 15;

    float acc[TM][TN];
    #pragma unroll
    for (int i = 0; i < TM; i++)
        #pragma unroll
        for (int j = 0; j < TN; j++) acc[i][j] = 0.f;

    int arow = tid >> 1, akk = (tid & 1) * 4;
    int brow = tid >> 5, bcol = (tid & 31) * 4;

    for (int k0 = 0; k0 < F1; k0 += BK) {
        float4 a = *(const float4*)&g_bufB[(size_t)(by * BM + arow) * F1 + k0 + akk];
        As[akk + 0][arow] = a.x; As[akk + 1][arow] = a.y;
        As[akk + 2][arow] = a.z; As[akk + 3][arow] = a.w;
        *(float4*)&Bs[brow][bcol] = *(const float4*)&W2[(size_t)(k0 + brow) * F1 + bx * BN + bcol];
        __syncthreads();
        #pragma unroll
        for (int kk = 0; kk < BK; kk++) {
            float4 a0 = *(float4*)&As[kk][ty * TM];
            float4 a1 = *(float4*)&As[kk][ty * TM + 4];
            float4 b0 = *(float4*)&Bs[kk][tx * TN];
            float4 b1 = *(float4*)&Bs[kk][tx * TN + 4];
            float ra[8] = {a0.x, a0.y, a0.z, a0.w, a1.x, a1.y, a1.z, a1.w};
            float rb[8] = {b0.x, b0.y, b0.z, b0.w, b1.x, b1.y, b1.z, b1.w};
            #pragma unroll
            for (int i = 0; i < TM; i++)
                #pragma unroll
                for (int j = 0; j < TN; j++) acc[i][j] += ra[i] * rb[j];
        }
        __syncthreads();
    }
    #pragma unroll
    for (int i = 0; i < TM; i++) {
        size_t row = (size_t)(by * BM + ty * TM + i);
        float4 c0 = {acc[i][0], acc[i][1], acc[i][2], acc[i][3]};
        float4 c1 = {acc[i][4], acc[i][5], acc[i][6], acc[i][7]};
        float4* cp = (float4*)&g_bufA[row * F1 + bx * BN + tx * TN];
        cp[0] = c0; cp[1] = c1;
    }
}

// ---------------- final: act2[50000,64] @ Wc[64,8] + bc -> out ---------------
__global__ void k_final(const float* __restrict__ Wc, const float* __restrict__ bc,
                        float* __restrict__ out) {
    __shared__ float Ws[512];
    __shared__ float bs[8];
    __shared__ float xs[32 * 64];
    int tid = threadIdx.x;
    Ws[tid] = Wc[tid];
    Ws[tid + 256] = Wc[tid + 256];
    if (tid < 8) bs[tid] = bc[tid];
    int r0 = blockIdx.x * 32;
    for (int i = tid; i < 2048; i += 256) {
        int g = r0 * HID + i;
        xs[i] = (g < N_NODES * HID) ? g_bufB[g] : 0.f;
    }
    __syncthreads();
    int r = tid >> 3, o = tid & 7;
    float acc = bs[o];
    #pragma unroll
    for (int c = 0; c < HID; c++) acc += xs[r * HID + c] * Ws[c * 8 + o];
    int row = r0 + r;
    if (row < N_NODES) out[row * OUT_CH + o] = acc;
}

// ---------------- launch -----------------------------------------------------
extern "C" void kernel_launch(void* const* d_in, const int* in_sizes, int n_in,
                              void* d_out, int out_size) {
    const float* x   = (const float*)d_in[0];
    const void*  ei  = d_in[1];
    const float* W1  = (const float*)d_in[2];
    const float* as1 = (const float*)d_in[3];
    const float* ad1 = (const float*)d_in[4];
    const float* b1  = (const float*)d_in[5];
    const float* W2  = (const float*)d_in[6];
    const float* as2 = (const float*)d_in[7];
    const float* ad2 = (const float*)d_in[8];
    const float* b2  = (const float*)d_in[9];
    const float* Wc  = (const float*)d_in[10];
    const float* bc  = (const float*)d_in[11];
    float* out = (float*)d_out;

    // CSR build
    k_init<<<(N_NODES + 255) / 256, 256>>>();
    k_detect<<<1, 32>>>(ei);
    k_count<<<(EA + 255) / 256, 256>>>(ei);
    k_scan<<<1, 1024>>>();
    k_scatter<<<(EA + 255) / 256, 256>>>(ei);

    // layer 1
    k_gemm1<<<M_PAD / 16, 256>>>(x, W1);
    k_alpha<<<(N_NODES * HEADS + 7) / 8, 256>>>(as1, ad1);
    k_edge_agg<1><<<(N_NODES + 7) / 8, 256>>>(b1);

    // layer 2
    dim3 g2(F1 / BN, M_PAD / BM);
    k_gemm2<<<g2, 256>>>(W2);
    k_alpha<<<(N_NODES * HEADS + 7) / 8, 256>>>(as2, ad2);
    k_edge_agg<2><<<(N_NODES + 7) / 8, 256>>>(b2);

    // classifier
    k_final<<<(N_NODES + 31) / 32, 256>>>(Wc, bc, out);
}

// round 3
// speedup vs baseline: 1.2192x; 1.2192x over previous
#include <cuda_runtime.h>
#include <cuda_bf16.h>
#include <cstdint>

#define N_NODES 50000
#define N_EDGES 800000
#define EA (N_EDGES + N_NODES)      // 850000 edges incl. self loops
#define M_PAD 50048                  // 391 * 128
#define IN_CH 16
#define HID 64
#define HEADS 4
#define F1 256                       // HEADS*HID
#define OUT_CH 8
#define NEG_SLOPE 0.2f
#define NB_SCAN 49                   // ceil(50000/1024)

// ---------------- device scratch (static; no allocations allowed) ------------
__device__ float g_bufA[(size_t)M_PAD * F1];   // h (gemm output) both layers
__device__ float g_bufB[(size_t)M_PAD * F1];   // act1 (256-wide) then act2 (64-wide)
__device__ float g_asrc[(size_t)M_PAD * HEADS];
__device__ float g_adst[(size_t)M_PAD * HEADS];
__device__ __align__(16) uint32_t g_Bhi[F1 * F1 / 2];  // W2^T hi, packed bf16x2 [n][k/2]
__device__ __align__(16) uint32_t g_Blo[F1 * F1 / 2];  // W2^T lo
__device__ int   g_rowptr[N_NODES + 1];
__device__ int   g_cursor[N_NODES];
__device__ int   g_count[N_NODES];
__device__ int   g_bsum[NB_SCAN];
__device__ int   g_boff[NB_SCAN];
__device__ int   g_csr_src[EA];
__device__ int   g_is64;

// ---------------- small helpers ---------------------------------------------
__device__ __forceinline__ float lrelu(float x) { return x > 0.f ? x : NEG_SLOPE * x; }
__device__ __forceinline__ float elu(float x)   { return x > 0.f ? x : expm1f(x); }

__device__ __forceinline__ uint32_t pack_bf(float a, float b) {
    __nv_bfloat162 t;
    t.x = __float2bfloat16_rn(a);
    t.y = __float2bfloat16_rn(b);
    return *(uint32_t*)&t;
}

// mma.sync m16n8k16 bf16 (sm_80+ PTX; compiles on plain sm_103 target)
__device__ __forceinline__ void mma_bf16(float* d, const uint32_t* a, const uint32_t* b) {
    asm volatile(
        "mma.sync.aligned.m16n8k16.row.col.f32.bf16.bf16.f32 "
        "{%0,%1,%2,%3}, {%4,%5,%6,%7}, {%8,%9}, {%0,%1,%2,%3};"
        : "+f"(d[0]), "+f"(d[1]), "+f"(d[2]), "+f"(d[3])
        : "r"(a[0]), "r"(a[1]), "r"(a[2]), "r"(a[3]), "r"(b[0]), "r"(b[1]));
}

// ---------------- init: zero counts + pad rows of bufB -----------------------
__global__ void k_init() {
    int i = blockIdx.x * blockDim.x + threadIdx.x;
    if (i < N_NODES) g_count[i] = 0;
    if (i < (M_PAD - N_NODES) * F1) g_bufB[(size_t)N_NODES * F1 + i] = 0.f;
}

// ---------------- detect edge_index dtype (int32 vs int64) -------------------
__global__ void k_detect(const void* ei) {
    if (threadIdx.x == 0) {
        const int* e32 = (const int*)ei;
        bool is64 = true;
        #pragma unroll
        for (int j = 0; j < 16; j++)
            if (e32[2 * j + 1] != 0) is64 = false;
        g_is64 = is64 ? 1 : 0;
    }
}

__device__ __forceinline__ void load_edge(const void* ei, int i, int& s, int& d) {
    if (i < N_EDGES) {
        if (g_is64) {
            const long long* e = (const long long*)ei;
            s = (int)e[i]; d = (int)e[N_EDGES + i];
        } else {
            const int* e = (const int*)ei;
            s = e[i]; d = e[N_EDGES + i];
        }
    } else {
        s = d = i - N_EDGES;   // self loop
    }
}

// ---------------- CSR build --------------------------------------------------
__global__ void k_count(const void* ei) {
    int i = blockIdx.x * blockDim.x + threadIdx.x;
    if (i >= EA) return;
    int s, d; load_edge(ei, i, s, d);
    atomicAdd(&g_count[d], 1);
}

// hierarchical scan: 49 blocks x 1024
__global__ void k_scan1() {
    __shared__ int wsum[32];
    int i = blockIdx.x * 1024 + threadIdx.x;
    int lane = threadIdx.x & 31, wid = threadIdx.x >> 5;
    int v = (i < N_NODES) ? g_count[i] : 0;
    int x = v;
    #pragma unroll
    for (int o = 1; o < 32; o <<= 1) {
        int t = __shfl_up_sync(~0u, x, o);
        if (lane >= o) x += t;
    }
    if (lane == 31) wsum[wid] = x;
    __syncthreads();
    if (wid == 0) {
        int y = wsum[lane];
        #pragma unroll
        for (int o = 1; o < 32; o <<= 1) {
            int t = __shfl_up_sync(~0u, y, o);
            if (lane >= o) y += t;
        }
        wsum[lane] = y;
    }
    __syncthreads();
    int excl = x - v + (wid ? wsum[wid - 1] : 0);
    if (i < N_NODES) g_rowptr[i] = excl;
    if (threadIdx.x == 0) g_bsum[blockIdx.x] = wsum[31];
}

__global__ void k_scan2() {   // 64 threads, 1 block
    __shared__ int s[64];
    int t = threadIdx.x;
    s[t] = (t < NB_SCAN) ? g_bsum[t] : 0;
    __syncthreads();
    if (t == 0) {
        int acc = 0;
        for (int b = 0; b < NB_SCAN; b++) { int v = s[b]; s[b] = acc; acc += v; }
        g_rowptr[N_NODES] = acc;
    }
    __syncthreads();
    if (t < NB_SCAN) g_boff[t] = s[t];
}

__global__ void k_scan3() {
    int i = blockIdx.x * blockDim.x + threadIdx.x;
    if (i >= N_NODES) return;
    int r = g_rowptr[i] + g_boff[i >> 10];
    g_rowptr[i] = r;
    g_cursor[i] = r;
}

__global__ void k_scatter(const void* ei) {
    int i = blockIdx.x * blockDim.x + threadIdx.x;
    if (i >= EA) return;
    int s, d; load_edge(ei, i, s, d);
    int pos = atomicAdd(&g_cursor[d], 1);
    g_csr_src[pos] = s;
}

// ---------------- W2 transpose + bf16 hi/lo split ----------------------------
// g_Bhi/g_Blo: [n][k/2] packed bf16x2 — exactly the B-fragment layout for
// mma.sync m16n8k16 row.col.
__global__ void k_w2split(const float* __restrict__ W2) {
    int i = blockIdx.x * blockDim.x + threadIdx.x;   // 32768 threads
    if (i >= F1 * F1 / 2) return;
    int n = i >> 7, kp = i & 127;
    int k = kp * 2;
    float w0 = W2[(size_t)k * F1 + n];
    float w1 = W2[(size_t)(k + 1) * F1 + n];
    __nv_bfloat16 h0 = __float2bfloat16_rn(w0);
    __nv_bfloat16 h1 = __float2bfloat16_rn(w1);
    float l0 = w0 - __bfloat162float(h0);
    float l1 = w1 - __bfloat162float(h1);
    __nv_bfloat162 hp; hp.x = h0; hp.y = h1;
    g_Bhi[n * 128 + kp] = *(uint32_t*)&hp;
    g_Blo[n * 128 + kp] = pack_bf(l0, l1);
}

// ---------------- GEMM1: x[50000,16] @ W1[16,256] -> bufA --------------------
__global__ void k_gemm1(const float* __restrict__ x, const float* __restrict__ W1) {
    __shared__ float Ws[16 * 256];
    __shared__ float xs[16 * 16];
    int tid = threadIdx.x;
    int r0 = blockIdx.x * 16;
    for (int i = tid; i < 16 * 256; i += 256) Ws[i] = W1[i];
    {
        int r = r0 + (tid >> 4), c = tid & 15;
        xs[tid] = (r < N_NODES) ? x[r * IN_CH + c] : 0.f;
    }
    __syncthreads();
    for (int rr = 0; rr < 16; rr++) {
        float acc = 0.f;
        #pragma unroll
        for (int k = 0; k < 16; k++) acc += xs[rr * 16 + k] * Ws[k * 256 + tid];
        g_bufA[(size_t)(r0 + rr) * F1 + tid] = acc;
    }
}

// ---------------- alpha: per (node, head) dot products on bufA ---------------
__global__ void k_alpha(const float* __restrict__ a_src, const float* __restrict__ a_dst) {
    int gw = (blockIdx.x * blockDim.x + threadIdx.x) >> 5;
    int lane = threadIdx.x & 31;
    if (gw >= N_NODES * HEADS) return;
    int n = gw >> 2, hh = gw & 3;
    const float* hp = g_bufA + (size_t)n * F1 + hh * HID;
    const float* as = a_src + hh * HID;
    const float* ad = a_dst + hh * HID;
    float x0 = hp[lane], x1 = hp[lane + 32];
    float ps = x0 * as[lane] + x1 * as[lane + 32];
    float pd = x0 * ad[lane] + x1 * ad[lane + 32];
    #pragma unroll
    for (int o = 16; o; o >>= 1) {
        ps += __shfl_xor_sync(~0u, ps, o);
        pd += __shfl_xor_sync(~0u, pd, o);
    }
    if (lane == 0) { g_asrc[n * 4 + hh] = ps; g_adst[n * 4 + hh] = pd; }
}

// ---------------- edge aggregation: one warp per destination node ------------
template <int LAYER>
__global__ void k_edge_agg(const float* __restrict__ bias) {
    int warp = (blockIdx.x * blockDim.x + threadIdx.x) >> 5;
    int lane = threadIdx.x & 31;
    if (warp >= N_NODES) return;
    int dst = warp;
    int beg = g_rowptr[dst], end = g_rowptr[dst + 1];
    int hh = lane >> 3;
    float ad = g_adst[dst * 4 + hh];

    float m = -3.0e38f;
    for (int k = beg + (lane & 7); k < end; k += 8) {
        int s = g_csr_src[k];
        float e = lrelu(g_asrc[s * 4 + hh] + ad);
        m = fmaxf(m, e);
    }
    m = fmaxf(m, __shfl_xor_sync(~0u, m, 1));
    m = fmaxf(m, __shfl_xor_sync(~0u, m, 2));
    m = fmaxf(m, __shfl_xor_sync(~0u, m, 4));

    float acc[8] = {0, 0, 0, 0, 0, 0, 0, 0};
    float den = 0.f;
    for (int k = beg; k < end; k++) {
        int s = g_csr_src[k];
        float e = lrelu(g_asrc[s * 4 + hh] + ad);
        float w = __expf(e - m);
        den += w;
        const float4* hr = (const float4*)(g_bufA + (size_t)s * F1 + lane * 8);
        float4 p = hr[0], q = hr[1];
        acc[0] += p.x * w; acc[1] += p.y * w; acc[2] += p.z * w; acc[3] += p.w * w;
        acc[4] += q.x * w; acc[5] += q.y * w; acc[6] += q.z * w; acc[7] += q.w * w;
    }
    float inv = 1.f / den;

    if (LAYER == 1) {
        int c = lane * 8;
        float4 o0, o1;
        o0.x = elu(acc[0] * inv + bias[c + 0]);
        o0.y = elu(acc[1] * inv + bias[c + 1]);
        o0.z = elu(acc[2] * inv + bias[c + 2]);
        o0.w = elu(acc[3] * inv + bias[c + 3]);
        o1.x = elu(acc[4] * inv + bias[c + 4]);
        o1.y = elu(acc[5] * inv + bias[c + 5]);
        o1.z = elu(acc[6] * inv + bias[c + 6]);
        o1.w = elu(acc[7] * inv + bias[c + 7]);
        float4* op = (float4*)(g_bufB + (size_t)dst * F1 + c);
        op[0] = o0; op[1] = o1;
    } else {
        float v[8];
        #pragma unroll
        for (int j = 0; j < 8; j++) {
            v[j] = acc[j] * inv;
            v[j] += __shfl_xor_sync(~0u, v[j], 8);
            v[j] += __shfl_xor_sync(~0u, v[j], 16);
        }
        if (lane < 8) {
            int c = lane * 8;
            float4 o0, o1;
            o0.x = elu(v[0] * 0.25f + bias[c + 0]);
            o0.y = elu(v[1] * 0.25f + bias[c + 1]);
            o0.z = elu(v[2] * 0.25f + bias[c + 2]);
            o0.w = elu(v[3] * 0.25f + bias[c + 3]);
            o1.x = elu(v[4] * 0.25f + bias[c + 4]);
            o1.y = elu(v[5] * 0.25f + bias[c + 5]);
            o1.z = elu(v[6] * 0.25f + bias[c + 6]);
            o1.w = elu(v[7] * 0.25f + bias[c + 7]);
            float4* op = (float4*)(g_bufB + (size_t)dst * HID + c);
            op[0] = o0; op[1] = o1;
        }
    }
}

// ---------------- GEMM2 (mma.sync bf16, 3-term compensated split) ------------
// D[128x128 per CTA] = bufB @ W2  with A=Ahi+Alo, B=Bhi+Blo,
// D ≈ AhiBhi + AhiBlo + AloBhi   (error ~2^-16)
// 8 warps: warp_m = w&3 (32-row slice), warp_n = w>>2 (64-col slice).
// Warp tile 32x64 = 2 x 8 m16n8 fragments, acc[2][8][4].
__global__ void __launch_bounds__(256) k_gemm2_mma() {
    __shared__ uint32_t Ah[128][17], Al[128][17];   // 32 bf16 (16 u32) per row + pad
    __shared__ uint32_t Bh[128][17], Bl[128][17];

    int tid = threadIdx.x;
    int warp = tid >> 5, lane = tid & 31;
    int wm = warp & 3, wn = warp >> 2;
    int g = lane >> 2, tg = lane & 3;
    int bx = blockIdx.x;                 // 0..1
    int by = blockIdx.y;                 // 0..390

    float acc[2][8][4];
    #pragma unroll
    for (int i = 0; i < 2; i++)
        #pragma unroll
        for (int j = 0; j < 8; j++)
            #pragma unroll
            for (int q = 0; q < 4; q++) acc[i][j][q] = 0.f;

    int arow = tid >> 1, ahalf = tid & 1;      // A stage: 16 floats per thread
    const float4* asrc = (const float4*)(g_bufB + (size_t)(by * 128 + arow) * F1 + ahalf * 16);
    const uint4* bhsrc = (const uint4*)(g_Bhi + (size_t)(bx * 128 + arow) * 128 + ahalf * 8);
    const uint4* blsrc = (const uint4*)(g_Blo + (size_t)(bx * 128 + arow) * 128 + ahalf * 8);

    for (int kc = 0; kc < 8; kc++) {
        // stage A (fp32 -> bf16 hi/lo split)
        #pragma unroll
        for (int t = 0; t < 4; t++) {
            float4 a = asrc[kc * 8 + t];
            __nv_bfloat16 hx = __float2bfloat16_rn(a.x);
            __nv_bfloat16 hy = __float2bfloat16_rn(a.y);
            __nv_bfloat16 hz = __float2bfloat16_rn(a.z);
            __nv_bfloat16 hw = __float2bfloat16_rn(a.w);
            __nv_bfloat162 p0; p0.x = hx; p0.y = hy;
            __nv_bfloat162 p1; p1.x = hz; p1.y = hw;
            int col = ahalf * 8 + t * 2;
            Ah[arow][col + 0] = *(uint32_t*)&p0;
            Ah[arow][col + 1] = *(uint32_t*)&p1;
            Al[arow][col + 0] = pack_bf(a.x - __bfloat162float(hx), a.y - __bfloat162float(hy));
            Al[arow][col + 1] = pack_bf(a.z - __bfloat162float(hz), a.w - __bfloat162float(hw));
        }
        // stage B (pre-split bf16)
        {
            uint4 v0 = bhsrc[kc * 4 + 0], v1 = bhsrc[kc * 4 + 1];
            uint4 w0 = blsrc[kc * 4 + 0], w1 = blsrc[kc * 4 + 1];
            int col = ahalf * 8;
            Bh[arow][col + 0] = v0.x; Bh[arow][col + 1] = v0.y;
            Bh[arow][col + 2] = v0.z; Bh[arow][col + 3] = v0.w;
            Bh[arow][col + 4] = v1.x; Bh[arow][col + 5] = v1.y;
            Bh[arow][col + 6] = v1.z; Bh[arow][col + 7] = v1.w;
            Bl[arow][col + 0] = w0.x; Bl[arow][col + 1] = w0.y;
            Bl[arow][col + 2] = w0.z; Bl[arow][col + 3] = w0.w;
            Bl[arow][col + 4] = w1.x; Bl[arow][col + 5] = w1.y;
            Bl[arow][col + 6] = w1.z; Bl[arow][col + 7] = w1.w;
        }
        __syncthreads();

        #pragma unroll
        for (int ks = 0; ks < 2; ks++) {
            uint32_t afh[2][4], afl[2][4];
            #pragma unroll
            for (int i = 0; i < 2; i++) {
                int rb = wm * 32 + i * 16;
                afh[i][0] = Ah[rb + g][ks * 8 + tg];
                afh[i][1] = Ah[rb + g + 8][ks * 8 + tg];
                afh[i][2] = Ah[rb + g][ks * 8 + 4 + tg];
                afh[i][3] = Ah[rb + g + 8][ks * 8 + 4 + tg];
                afl[i][0] = Al[rb + g][ks * 8 + tg];
                afl[i][1] = Al[rb + g + 8][ks * 8 + tg];
                afl[i][2] = Al[rb + g][ks * 8 + 4 + tg];
                afl[i][3] = Al[rb + g + 8][ks * 8 + 4 + tg];
            }
            uint32_t bfh[8][2], bfl[8][2];
            #pragma unroll
            for (int j = 0; j < 8; j++) {
                int n = wn * 64 + j * 8 + g;
                bfh[j][0] = Bh[n][ks * 8 + tg];
                bfh[j][1] = Bh[n][ks * 8 + 4 + tg];
                bfl[j][0] = Bl[n][ks * 8 + tg];
                bfl[j][1] = Bl[n][ks * 8 + 4 + tg];
            }
            #pragma unroll
            for (int i = 0; i < 2; i++)
                #pragma unroll
                for (int j = 0; j < 8; j++) {
                    mma_bf16(acc[i][j], afh[i], bfh[j]);
                    mma_bf16(acc[i][j], afh[i], bfl[j]);
                    mma_bf16(acc[i][j], afl[i], bfh[j]);
                }
        }
        __syncthreads();
    }

    // epilogue
    #pragma unroll
    for (int i = 0; i < 2; i++) {
        int row0 = by * 128 + wm * 32 + i * 16 + g;
        #pragma unroll
        for (int j = 0; j < 8; j++) {
            int col = bx * 128 + wn * 64 + j * 8 + tg * 2;
            float2 v0 = {acc[i][j][0], acc[i][j][1]};
            float2 v1 = {acc[i][j][2], acc[i][j][3]};
            *(float2*)(g_bufA + (size_t)row0 * F1 + col) = v0;
            *(float2*)(g_bufA + (size_t)(row0 + 8) * F1 + col) = v1;
        }
    }
}

// ---------------- final: act2[50000,64] @ Wc[64,8] + bc -> out ---------------
__global__ void k_final(const float* __restrict__ Wc, const float* __restrict__ bc,
                        float* __restrict__ out) {
    __shared__ float Ws[512];
    __shared__ float bs[8];
    __shared__ float xs[32 * 64];
    int tid = threadIdx.x;
    Ws[tid] = Wc[tid];
    Ws[tid + 256] = Wc[tid + 256];
    if (tid < 8) bs[tid] = bc[tid];
    int r0 = blockIdx.x * 32;
    for (int i = tid; i < 2048; i += 256) {
        int g = r0 * HID + i;
        xs[i] = (g < N_NODES * HID) ? g_bufB[g] : 0.f;
    }
    __syncthreads();
    int r = tid >> 3, o = tid & 7;
    float acc = bs[o];
    #pragma unroll
    for (int c = 0; c < HID; c++) acc += xs[r * HID + c] * Ws[c * 8 + o];
    int row = r0 + r;
    if (row < N_NODES) out[row * OUT_CH + o] = acc;
}

// ---------------- launch -----------------------------------------------------
extern "C" void kernel_launch(void* const* d_in, const int* in_sizes, int n_in,
                              void* d_out, int out_size) {
    const float* x   = (const float*)d_in[0];
    const void*  ei  = d_in[1];
    const float* W1  = (const float*)d_in[2];
    const float* as1 = (const float*)d_in[3];
    const float* ad1 = (const float*)d_in[4];
    const float* b1  = (const float*)d_in[5];
    const float* W2  = (const float*)d_in[6];
    const float* as2 = (const float*)d_in[7];
    const float* ad2 = (const float*)d_in[8];
    const float* b2  = (const float*)d_in[9];
    const float* Wc  = (const float*)d_in[10];
    const float* bc  = (const float*)d_in[11];
    float* out = (float*)d_out;

    // CSR build
    k_init<<<(N_NODES + 255) / 256, 256>>>();
    k_detect<<<1, 32>>>(ei);
    k_count<<<(EA + 255) / 256, 256>>>(ei);
    k_scan1<<<NB_SCAN, 1024>>>();
    k_scan2<<<1, 64>>>();
    k_scan3<<<(N_NODES + 255) / 256, 256>>>();
    k_scatter<<<(EA + 255) / 256, 256>>>(ei);

    // W2 split (independent of everything above)
    k_w2split<<<(F1 * F1 / 2 + 255) / 256, 256>>>(W2);

    // layer 1
    k_gemm1<<<M_PAD / 16, 256>>>(x, W1);
    k_alpha<<<(N_NODES * HEADS + 7) / 8, 256>>>(as1, ad1);
    k_edge_agg<1><<<(N_NODES + 7) / 8, 256>>>(b1);

    // layer 2
    dim3 g2(2, M_PAD / 128);
    k_gemm2_mma<<<g2, 256>>>();
    k_alpha<<<(N_NODES * HEADS + 7) / 8, 256>>>(as2, ad2);
    k_edge_agg<2><<<(N_NODES + 7) / 8, 256>>>(b2);

    // classifier
    k_final<<<(N_NODES + 31) / 32, 256>>>(Wc, bc, out);
}

// round 5
// speedup vs baseline: 1.4214x; 1.1658x over previous
#include <cuda_runtime.h>
#include <cuda_bf16.h>
#include <cuda_fp16.h>
#include <cstdint>

#define N_NODES 50000
#define N_EDGES 800000
#define EA (N_EDGES + N_NODES)      // 850000 edges incl. self loops
#define M_PAD 50048                  // 391 * 128
#define IN_CH 16
#define HID 64
#define HEADS 4
#define F1 256                       // HEADS*HID
#define OUT_CH 8
#define NEG_SLOPE 0.2f
#define NB_SCAN 49                   // ceil(50000/1024)

// ---------------- device scratch (static; no allocations allowed) ------------
__device__ __align__(16) __half g_h[(size_t)M_PAD * F1];   // h in fp16 (both layers)
__device__ float g_bufB[(size_t)M_PAD * F1];   // act1 (256-wide) then act2 (64-wide)
__device__ float g_asrc[(size_t)M_PAD * HEADS];
__device__ float g_adst[(size_t)M_PAD * HEADS];
__device__ __align__(16) uint32_t g_Bhi[F1 * F1 / 2];  // W2^T hi, packed bf16x2 [n][k/2]
__device__ __align__(16) uint32_t g_Blo[F1 * F1 / 2];  // W2^T lo
__device__ int   g_rowptr[N_NODES + 1];
__device__ int   g_cursor[N_NODES];
__device__ int   g_count[N_NODES];
__device__ int   g_bsum[NB_SCAN];
__device__ int   g_boff[NB_SCAN];
__device__ int   g_csr_src[EA];
__device__ int   g_is64;

// ---------------- small helpers ---------------------------------------------
__device__ __forceinline__ float lrelu(float x) { return x > 0.f ? x : NEG_SLOPE * x; }
__device__ __forceinline__ float elu(float x)   { return x > 0.f ? x : expm1f(x); }

__device__ __forceinline__ uint32_t pack_bf(float a, float b) {
    __nv_bfloat162 t;
    t.x = __float2bfloat16_rn(a);
    t.y = __float2bfloat16_rn(b);
    return *(uint32_t*)&t;
}
__device__ __forceinline__ uint32_t pack_h(float a, float b) {
    __half2 t;
    t.x = __float2half_rn(a);
    t.y = __float2half_rn(b);
    return *(uint32_t*)&t;
}

// mma.sync m16n8k16 bf16 (sm_80+ PTX; compiles on plain sm_103 target)
__device__ __forceinline__ void mma_bf16(float* d, const uint32_t* a, const uint32_t* b) {
    asm volatile(
        "mma.sync.aligned.m16n8k16.row.col.f32.bf16.bf16.f32 "
        "{%0,%1,%2,%3}, {%4,%5,%6,%7}, {%8,%9}, {%0,%1,%2,%3};"
        : "+f"(d[0]), "+f"(d[1]), "+f"(d[2]), "+f"(d[3])
        : "r"(a[0]), "r"(a[1]), "r"(a[2]), "r"(a[3]), "r"(b[0]), "r"(b[1]));
}

// ---------------- init kernels ----------------------------------------------
__global__ void k_zero_count() {
    int i = blockIdx.x * blockDim.x + threadIdx.x;
    if (i < N_NODES) g_count[i] = 0;
}
__global__ void k_pad() {   // zero pad rows of bufB (rows N_NODES..M_PAD)
    int i = blockIdx.x * blockDim.x + threadIdx.x;
    if (i < (M_PAD - N_NODES) * F1) g_bufB[(size_t)N_NODES * F1 + i] = 0.f;
}

// ---------------- detect edge_index dtype (int32 vs int64) -------------------
__global__ void k_detect(const void* ei) {
    if (threadIdx.x == 0) {
        const int* e32 = (const int*)ei;
        bool is64 = true;
        #pragma unroll
        for (int j = 0; j < 16; j++)
            if (e32[2 * j + 1] != 0) is64 = false;
        g_is64 = is64 ? 1 : 0;
    }
}

__device__ __forceinline__ void load_edge(const void* ei, int i, int& s, int& d) {
    if (i < N_EDGES) {
        if (g_is64) {
            const long long* e = (const long long*)ei;
            s = (int)e[i]; d = (int)e[N_EDGES + i];
        } else {
            const int* e = (const int*)ei;
            s = e[i]; d = e[N_EDGES + i];
        }
    } else {
        s = d = i - N_EDGES;   // self loop
    }
}

// ---------------- CSR build --------------------------------------------------
__global__ void k_count(const void* ei) {
    int i = blockIdx.x * blockDim.x + threadIdx.x;
    if (i >= EA) return;
    int s, d; load_edge(ei, i, s, d);
    atomicAdd(&g_count[d], 1);
}

// hierarchical scan: 49 blocks x 1024
__global__ void k_scan1() {
    __shared__ int wsum[32];
    int i = blockIdx.x * 1024 + threadIdx.x;
    int lane = threadIdx.x & 31, wid = threadIdx.x >> 5;
    int v = (i < N_NODES) ? g_count[i] : 0;
    int x = v;
    #pragma unroll
    for (int o = 1; o < 32; o <<= 1) {
        int t = __shfl_up_sync(~0u, x, o);
        if (lane >= o) x += t;
    }
    if (lane == 31) wsum[wid] = x;
    __syncthreads();
    if (wid == 0) {
        int y = wsum[lane];
        #pragma unroll
        for (int o = 1; o < 32; o <<= 1) {
            int t = __shfl_up_sync(~0u, y, o);
            if (lane >= o) y += t;
        }
        wsum[lane] = y;
    }
    __syncthreads();
    int excl = x - v + (wid ? wsum[wid - 1] : 0);
    if (i < N_NODES) g_rowptr[i] = excl;
    if (threadIdx.x == 0) g_bsum[blockIdx.x] = wsum[31];
}

__global__ void k_scan2() {   // 64 threads, 1 block
    __shared__ int s[64];
    int t = threadIdx.x;
    s[t] = (t < NB_SCAN) ? g_bsum[t] : 0;
    __syncthreads();
    if (t == 0) {
        int acc = 0;
        for (int b = 0; b < NB_SCAN; b++) { int v = s[b]; s[b] = acc; acc += v; }
        g_rowptr[N_NODES] = acc;
    }
    __syncthreads();
    if (t < NB_SCAN) g_boff[t] = s[t];
}

__global__ void k_scan3() {
    int i = blockIdx.x * blockDim.x + threadIdx.x;
    if (i >= N_NODES) return;
    int r = g_rowptr[i] + g_boff[i >> 10];
    g_rowptr[i] = r;
    g_cursor[i] = r;
}

__global__ void k_scatter(const void* ei) {
    int i = blockIdx.x * blockDim.x + threadIdx.x;
    if (i >= EA) return;
    int s, d; load_edge(ei, i, s, d);
    int pos = atomicAdd(&g_cursor[d], 1);
    g_csr_src[pos] = s;
}

// ---------------- W2 transpose + bf16 hi/lo split ----------------------------
__global__ void k_w2split(const float* __restrict__ W2) {
    int i = blockIdx.x * blockDim.x + threadIdx.x;   // 32768 threads
    if (i >= F1 * F1 / 2) return;
    int n = i >> 7, kp = i & 127;
    int k = kp * 2;
    float w0 = W2[(size_t)k * F1 + n];
    float w1 = W2[(size_t)(k + 1) * F1 + n];
    __nv_bfloat16 h0 = __float2bfloat16_rn(w0);
    __nv_bfloat16 h1 = __float2bfloat16_rn(w1);
    float l0 = w0 - __bfloat162float(h0);
    float l1 = w1 - __bfloat162float(h1);
    __nv_bfloat162 hp; hp.x = h0; hp.y = h1;
    g_Bhi[n * 128 + kp] = *(uint32_t*)&hp;
    g_Blo[n * 128 + kp] = pack_bf(l0, l1);
}

// ---------------- GEMM1: x[50000,16] @ W1[16,256] -> g_h (fp16) --------------
__global__ void k_gemm1(const float* __restrict__ x, const float* __restrict__ W1) {
    __shared__ float Ws[16 * 256];
    __shared__ float xs[16 * 16];
    int tid = threadIdx.x;
    int r0 = blockIdx.x * 16;
    for (int i = tid; i < 16 * 256; i += 256) Ws[i] = W1[i];
    {
        int r = r0 + (tid >> 4), c = tid & 15;
        xs[tid] = (r < N_NODES) ? x[r * IN_CH + c] : 0.f;
    }
    __syncthreads();
    for (int rr = 0; rr < 16; rr++) {
        float acc = 0.f;
        #pragma unroll
        for (int k = 0; k < 16; k++) acc += xs[rr * 16 + k] * Ws[k * 256 + tid];
        g_h[(size_t)(r0 + rr) * F1 + tid] = __float2half_rn(acc);
    }
}

// ---------------- alpha: per (node, head) dot products on g_h ----------------
__global__ void k_alpha(const float* __restrict__ a_src, const float* __restrict__ a_dst) {
    int gw = (blockIdx.x * blockDim.x + threadIdx.x) >> 5;
    int lane = threadIdx.x & 31;
    if (gw >= N_NODES * HEADS) return;
    int n = gw >> 2, hh = gw & 3;
    const __half* hp = g_h + (size_t)n * F1 + hh * HID;
    const float* as = a_src + hh * HID;
    const float* ad = a_dst + hh * HID;
    __half2 hv = *(const __half2*)(hp + lane * 2);
    float2 f = __half22float2(hv);
    float a0 = as[lane * 2], a1 = as[lane * 2 + 1];
    float d0 = ad[lane * 2], d1 = ad[lane * 2 + 1];
    float ps = f.x * a0 + f.y * a1;
    float pd = f.x * d0 + f.y * d1;
    #pragma unroll
    for (int o = 16; o; o >>= 1) {
        ps += __shfl_xor_sync(~0u, ps, o);
        pd += __shfl_xor_sync(~0u, pd, o);
    }
    if (lane == 0) { g_asrc[n * 4 + hh] = ps; g_adst[n * 4 + hh] = pd; }
}

// ---------------- edge aggregation: one warp per destination node ------------
// gathers fp16 h rows (512B/edge); fp32 accumulation
template <int LAYER>
__global__ void k_edge_agg(const float* __restrict__ bias) {
    int warp = (blockIdx.x * blockDim.x + threadIdx.x) >> 5;
    int lane = threadIdx.x & 31;
    if (warp >= N_NODES) return;
    int dst = warp;
    int beg = g_rowptr[dst], end = g_rowptr[dst + 1];
    int hh = lane >> 3;
    float ad = g_adst[dst * 4 + hh];

    float m = -3.0e38f;
    for (int k = beg + (lane & 7); k < end; k += 8) {
        int s = g_csr_src[k];
        float e = lrelu(g_asrc[s * 4 + hh] + ad);
        m = fmaxf(m, e);
    }
    m = fmaxf(m, __shfl_xor_sync(~0u, m, 1));
    m = fmaxf(m, __shfl_xor_sync(~0u, m, 2));
    m = fmaxf(m, __shfl_xor_sync(~0u, m, 4));

    float acc[8] = {0, 0, 0, 0, 0, 0, 0, 0};
    float den = 0.f;
    for (int k = beg; k < end; k++) {
        int s = g_csr_src[k];
        float e = lrelu(g_asrc[s * 4 + hh] + ad);
        float w = __expf(e - m);
        den += w;
        uint4 v = *(const uint4*)(g_h + (size_t)s * F1 + lane * 8);
        float2 f0 = __half22float2(*(__half2*)&v.x);
        float2 f1 = __half22float2(*(__half2*)&v.y);
        float2 f2 = __half22float2(*(__half2*)&v.z);
        float2 f3 = __half22float2(*(__half2*)&v.w);
        acc[0] += f0.x * w; acc[1] += f0.y * w; acc[2] += f1.x * w; acc[3] += f1.y * w;
        acc[4] += f2.x * w; acc[5] += f2.y * w; acc[6] += f3.x * w; acc[7] += f3.y * w;
    }
    float inv = 1.f / den;

    if (LAYER == 1) {
        int c = lane * 8;
        float4 o0, o1;
        o0.x = elu(acc[0] * inv + bias[c + 0]);
        o0.y = elu(acc[1] * inv + bias[c + 1]);
        o0.z = elu(acc[2] * inv + bias[c + 2]);
        o0.w = elu(acc[3] * inv + bias[c + 3]);
        o1.x = elu(acc[4] * inv + bias[c + 4]);
        o1.y = elu(acc[5] * inv + bias[c + 5]);
        o1.z = elu(acc[6] * inv + bias[c + 6]);
        o1.w = elu(acc[7] * inv + bias[c + 7]);
        float4* op = (float4*)(g_bufB + (size_t)dst * F1 + c);
        op[0] = o0; op[1] = o1;
    } else {
        float v[8];
        #pragma unroll
        for (int j = 0; j < 8; j++) {
            v[j] = acc[j] * inv;
            v[j] += __shfl_xor_sync(~0u, v[j], 8);
            v[j] += __shfl_xor_sync(~0u, v[j], 16);
        }
        if (lane < 8) {
            int c = lane * 8;
            float4 o0, o1;
            o0.x = elu(v[0] * 0.25f + bias[c + 0]);
            o0.y = elu(v[1] * 0.25f + bias[c + 1]);
            o0.z = elu(v[2] * 0.25f + bias[c + 2]);
            o0.w = elu(v[3] * 0.25f + bias[c + 3]);
            o1.x = elu(v[4] * 0.25f + bias[c + 4]);
            o1.y = elu(v[5] * 0.25f + bias[c + 5]);
            o1.z = elu(v[6] * 0.25f + bias[c + 6]);
            o1.w = elu(v[7] * 0.25f + bias[c + 7]);
            float4* op = (float4*)(g_bufB + (size_t)dst * HID + c);
            op[0] = o0; op[1] = o1;
        }
    }
}

// ---------------- GEMM2 (mma.sync bf16, 3-term compensated split) ------------
__global__ void __launch_bounds__(256) k_gemm2_mma() {
    __shared__ uint32_t Ah[128][17], Al[128][17];
    __shared__ uint32_t Bh[128][17], Bl[128][17];

    int tid = threadIdx.x;
    int warp = tid >> 5, lane = tid & 31;
    int wm = warp & 3, wn = warp >> 2;
    int g = lane >> 2, tg = lane & 3;
    int bx = blockIdx.x;                 // 0..1
    int by = blockIdx.y;                 // 0..390

    float acc[2][8][4];
    #pragma unroll
    for (int i = 0; i < 2; i++)
        #pragma unroll
        for (int j = 0; j < 8; j++)
            #pragma unroll
            for (int q = 0; q < 4; q++) acc[i][j][q] = 0.f;

    int arow = tid >> 1, ahalf = tid & 1;
    const float4* asrc = (const float4*)(g_bufB + (size_t)(by * 128 + arow) * F1 + ahalf * 16);
    const uint4* bhsrc = (const uint4*)(g_Bhi + (size_t)(bx * 128 + arow) * 128 + ahalf * 8);
    const uint4* blsrc = (const uint4*)(g_Blo + (size_t)(bx * 128 + arow) * 128 + ahalf * 8);

    for (int kc = 0; kc < 8; kc++) {
        #pragma unroll
        for (int t = 0; t < 4; t++) {
            float4 a = asrc[kc * 8 + t];
            __nv_bfloat16 hx = __float2bfloat16_rn(a.x);
            __nv_bfloat16 hy = __float2bfloat16_rn(a.y);
            __nv_bfloat16 hz = __float2bfloat16_rn(a.z);
            __nv_bfloat16 hw = __float2bfloat16_rn(a.w);
            __nv_bfloat162 p0; p0.x = hx; p0.y = hy;
            __nv_bfloat162 p1; p1.x = hz; p1.y = hw;
            int col = ahalf * 8 + t * 2;
            Ah[arow][col + 0] = *(uint32_t*)&p0;
            Ah[arow][col + 1] = *(uint32_t*)&p1;
            Al[arow][col + 0] = pack_bf(a.x - __bfloat162float(hx), a.y - __bfloat162float(hy));
            Al[arow][col + 1] = pack_bf(a.z - __bfloat162float(hz), a.w - __bfloat162float(hw));
        }
        {
            uint4 v0 = bhsrc[kc * 4 + 0], v1 = bhsrc[kc * 4 + 1];
            uint4 w0 = blsrc[kc * 4 + 0], w1 = blsrc[kc * 4 + 1];
            int col = ahalf * 8;
            Bh[arow][col + 0] = v0.x; Bh[arow][col + 1] = v0.y;
            Bh[arow][col + 2] = v0.z; Bh[arow][col + 3] = v0.w;
            Bh[arow][col + 4] = v1.x; Bh[arow][col + 5] = v1.y;
            Bh[arow][col + 6] = v1.z; Bh[arow][col + 7] = v1.w;
            Bl[arow][col + 0] = w0.x; Bl[arow][col + 1] = w0.y;
            Bl[arow][col + 2] = w0.z; Bl[arow][col + 3] = w0.w;
            Bl[arow][col + 4] = w1.x; Bl[arow][col + 5] = w1.y;
            Bl[arow][col + 6] = w1.z; Bl[arow][col + 7] = w1.w;
        }
        __syncthreads();

        #pragma unroll
        for (int ks = 0; ks < 2; ks++) {
            uint32_t afh[2][4], afl[2][4];
            #pragma unroll
            for (int i = 0; i < 2; i++) {
                int rb = wm * 32 + i * 16;
                afh[i][0] = Ah[rb + g][ks * 8 + tg];
                afh[i][1] = Ah[rb + g + 8][ks * 8 + tg];
                afh[i][2] = Ah[rb + g][ks * 8 + 4 + tg];
                afh[i][3] = Ah[rb + g + 8][ks * 8 + 4 + tg];
                afl[i][0] = Al[rb + g][ks * 8 + tg];
                afl[i][1] = Al[rb + g + 8][ks * 8 + tg];
                afl[i][2] = Al[rb + g][ks * 8 + 4 + tg];
                afl[i][3] = Al[rb + g + 8][ks * 8 + 4 + tg];
            }
            uint32_t bfh[8][2], bfl[8][2];
            #pragma unroll
            for (int j = 0; j < 8; j++) {
                int n = wn * 64 + j * 8 + g;
                bfh[j][0] = Bh[n][ks * 8 + tg];
                bfh[j][1] = Bh[n][ks * 8 + 4 + tg];
                bfl[j][0] = Bl[n][ks * 8 + tg];
                bfl[j][1] = Bl[n][ks * 8 + 4 + tg];
            }
            #pragma unroll
            for (int i = 0; i < 2; i++)
                #pragma unroll
                for (int j = 0; j < 8; j++) {
                    mma_bf16(acc[i][j], afh[i], bfh[j]);
                    mma_bf16(acc[i][j], afh[i], bfl[j]);
                    mma_bf16(acc[i][j], afl[i], bfh[j]);
                }
        }
        __syncthreads();
    }

    // epilogue: write fp16 h2 directly
    #pragma unroll
    for (int i = 0; i < 2; i++) {
        int row0 = by * 128 + wm * 32 + i * 16 + g;
        #pragma unroll
        for (int j = 0; j < 8; j++) {
            int col = bx * 128 + wn * 64 + j * 8 + tg * 2;
            *(uint32_t*)(g_h + (size_t)row0 * F1 + col) = pack_h(acc[i][j][0], acc[i][j][1]);
            *(uint32_t*)(g_h + (size_t)(row0 + 8) * F1 + col) = pack_h(acc[i][j][2], acc[i][j][3]);
        }
    }
}

// ---------------- final: act2[50000,64] @ Wc[64,8] + bc -> out ---------------
__global__ void k_final(const float* __restrict__ Wc, const float* __restrict__ bc,
                        float* __restrict__ out) {
    __shared__ float Ws[512];
    __shared__ float bs[8];
    __shared__ float xs[32 * 64];
    int tid = threadIdx.x;
    Ws[tid] = Wc[tid];
    Ws[tid + 256] = Wc[tid + 256];
    if (tid < 8) bs[tid] = bc[tid];
    int r0 = blockIdx.x * 32;
    for (int i = tid; i < 2048; i += 256) {
        int g = r0 * HID + i;
        xs[i] = (g < N_NODES * HID) ? g_bufB[g] : 0.f;
    }
    __syncthreads();
    int r = tid >> 3, o = tid & 7;
    float acc = bs[o];
    #pragma unroll
    for (int c = 0; c < HID; c++) acc += xs[r * HID + c] * Ws[c * 8 + o];
    int row = r0 + r;
    if (row < N_NODES) out[row * OUT_CH + o] = acc;
}

// ---------------- launch -----------------------------------------------------
extern "C" void kernel_launch(void* const* d_in, const int* in_sizes, int n_in,
                              void* d_out, int out_size) {
    const float* x   = (const float*)d_in[0];
    const void*  ei  = d_in[1];
    const float* W1  = (const float*)d_in[2];
    const float* as1 = (const float*)d_in[3];
    const float* ad1 = (const float*)d_in[4];
    const float* b1  = (const float*)d_in[5];
    const float* W2  = (const float*)d_in[6];
    const float* as2 = (const float*)d_in[7];
    const float* ad2 = (const float*)d_in[8];
    const float* b2  = (const float*)d_in[9];
    const float* Wc  = (const float*)d_in[10];
    const float* bc  = (const float*)d_in[11];
    float* out = (float*)d_out;

    // one-time aux stream + events (host-side objects only; no device memory)
    static cudaStream_t s2 = nullptr;
    static cudaEvent_t evF = nullptr, evJ = nullptr;
    if (!s2) {
        cudaStreamCreate(&s2);
        cudaEventCreateWithFlags(&evF, cudaEventDisableTiming);
        cudaEventCreateWithFlags(&evJ, cudaEventDisableTiming);
    }

    // fork: CSR build chain on s2, concurrent with gemm1/alpha1/w2split on default
    cudaEventRecord(evF, 0);
    cudaStreamWaitEvent(s2, evF, 0);

    k_zero_count<<<(N_NODES + 255) / 256, 256, 0, s2>>>();
    k_detect<<<1, 32, 0, s2>>>(ei);
    k_count<<<(EA + 255) / 256, 256, 0, s2>>>(ei);
    k_scan1<<<NB_SCAN, 1024, 0, s2>>>();
    k_scan2<<<1, 64, 0, s2>>>();
    k_scan3<<<(N_NODES + 255) / 256, 256, 0, s2>>>();
    k_scatter<<<(EA + 255) / 256, 256, 0, s2>>>(ei);

    k_pad<<<((M_PAD - N_NODES) * F1 + 255) / 256, 256>>>();
    k_w2split<<<(F1 * F1 / 2 + 255) / 256, 256>>>(W2);
    k_gemm1<<<M_PAD / 16, 256>>>(x, W1);
    k_alpha<<<(N_NODES * HEADS + 7) / 8, 256>>>(as1, ad1);

    // join
    cudaEventRecord(evJ, s2);
    cudaStreamWaitEvent(0, evJ, 0);

    // layer 1 aggregation
    k_edge_agg<1><<<(N_NODES + 7) / 8, 256>>>(b1);

    // layer 2
    dim3 g2(2, M_PAD / 128);
    k_gemm2_mma<<<g2, 256>>>();
    k_alpha<<<(N_NODES * HEADS + 7) / 8, 256>>>(as2, ad2);
    k_edge_agg<2><<<(N_NODES + 7) / 8, 256>>>(b2);

    // classifier
    k_final<<<(N_NODES + 31) / 32, 256>>>(Wc, bc, out);
}